// round 6
// baseline (speedup 1.0000x reference)
#include <cuda_runtime.h>

// HashEncoder: D=3, L=16, C=2, BASE=16, PLS=2, T=2^19, B=2^21
// Levels 0..2 dense (res^3 <= T), levels 3..15 hashed into T=524288 entries.
// Output: [B, 32] float32, level-major channel pairs.
//
// Corner-pair trick: with ix0 clamped to res-2 (fx may reach 1.0 — identical
// math to the reference's corner clamp), the second x-corner index is i0^1
// whenever ix0 is even, in BOTH dense and hashed addressing. One aligned
// float4 load at (i0 & ~1) covers both x-corners for even-x lanes.
// All lo/hi disambiguation is folded into the WEIGHTS (computed pre-load),
// so the only instructions consuming a load result are FMAs.

#define NPOINTS  2097152
#define NLEV     16
#define TSIZE    524288u
#define HMASK    524287u
#define PRIME1   2654435761u
#define PRIME2   805459861u
#define BLOCK    256
#define SPITCH   36

__device__ static constexpr int OFFS[16] = {
    0, 4096, 36864, 299008,
    823296, 1347584, 1871872, 2396160,
    2920448, 3444736, 3969024, 4493312,
    5017600, 5541888, 6066176, 6590464
};

__global__ void __launch_bounds__(BLOCK)
hash_encode_kernel(const float* __restrict__ in,
                   const float* __restrict__ emb,
                   float* __restrict__ out)
{
    __shared__ float s_out[BLOCK * SPITCH];   // 36 KB

    const int tid = threadIdx.x;
    const long long p = (long long)blockIdx.x * BLOCK + tid;

    const float x = in[p * 3 + 0];
    const float y = in[p * 3 + 1];
    const float z = in[p * 3 + 2];

#pragma unroll
    for (int l = 0; l < NLEV; l++) {
        const int res = 16 << l;                 // exact: ceil(16 * 2^l)
        const float scale = (float)(res - 1);

        const float px = x * scale;
        const float py = y * scale;
        const float pz = z * scale;

        int ix0 = min(__float2int_rd(px), res - 2);
        int iy0 = min(__float2int_rd(py), res - 2);
        int iz0 = min(__float2int_rd(pz), res - 2);

        const float fx = px - (float)ix0;
        const float fy = py - (float)iy0;
        const float fz = pz - (float)iz0;

        const float wx0 = 1.0f - fx;
        const float wyz[4] = {(1.0f - fy) * (1.0f - fz),
                              fy * (1.0f - fz),
                              (1.0f - fy) * fz,
                              fy * fz};

        const float2* __restrict__ e = (const float2*)emb + OFFS[l];

        const bool dense = ((long long)res * res * res) <= (long long)TSIZE; // compile-time
        const unsigned ux0 = (unsigned)ix0;
        const bool xeven = (ux0 & 1u) == 0u;
        // Portion of fx that rides in the float4's other slot (even-x lanes);
        // odd-x lanes take corner 1 through the separate B load instead.
        const float fx_pair = xeven ? fx : 0.0f;

        unsigned yz[4];
        if (dense) {
            const unsigned r  = (unsigned)res;
            const unsigned r2 = r * r;
            yz[0] = (unsigned)iy0 * r        + (unsigned)iz0 * r2;
            yz[1] = ((unsigned)iy0 + 1u) * r + (unsigned)iz0 * r2;
            yz[2] = (unsigned)iy0 * r        + ((unsigned)iz0 + 1u) * r2;
            yz[3] = ((unsigned)iy0 + 1u) * r + ((unsigned)iz0 + 1u) * r2;
        } else {
            const unsigned hy0 = (unsigned)iy0 * PRIME1;
            const unsigned hy1 = ((unsigned)iy0 + 1u) * PRIME1;
            const unsigned hz0 = (unsigned)iz0 * PRIME2;
            const unsigned hz1 = ((unsigned)iz0 + 1u) * PRIME2;
            yz[0] = hy0 ^ hz0;
            yz[1] = hy1 ^ hz0;
            yz[2] = hy0 ^ hz1;
            yz[3] = hy1 ^ hz1;
        }

        float r0 = 0.0f, r1 = 0.0f;

        float4 Av[4];
        float2 Bv[4];
        float  wlo[4], whi[4], wB[4];

        // Phase 1: addresses + weights + all loads (max MLP, no consumers yet).
#pragma unroll
        for (int c = 0; c < 4; c++) {
            unsigned i0, i1;
            if (dense) { i0 = ux0 + yz[c];            i1 = i0 + 1u; }
            else       { i0 = (ux0 ^ yz[c]) & HMASK;  i1 = ((ux0 + 1u) ^ yz[c]) & HMASK; }

            const float w0   = wx0     * wyz[c];   // corner x0 weight
            const float wopp = fx_pair * wyz[c];   // corner x1 weight if in A
            const bool  hi   = (i0 & 1u) != 0u;
            wlo[c] = hi ? wopp : w0;
            whi[c] = hi ? w0   : wopp;
            wB[c]  = fx * wyz[c];                  // zero-effect when Bv==0

            Av[c] = __ldg((const float4*)(e + (i0 & ~1u)));
            Bv[c] = xeven ? make_float2(0.0f, 0.0f) : __ldg(e + i1);
        }

        // Phase 2: pure FMAs.
#pragma unroll
        for (int c = 0; c < 4; c++) {
            r0 = fmaf(wlo[c], Av[c].x, r0);
            r1 = fmaf(wlo[c], Av[c].y, r1);
            r0 = fmaf(whi[c], Av[c].z, r0);
            r1 = fmaf(whi[c], Av[c].w, r1);
            r0 = fmaf(wB[c],  Bv[c].x, r0);
            r1 = fmaf(wB[c],  Bv[c].y, r1);
        }

        *(float2*)&s_out[tid * SPITCH + 2 * l] = make_float2(r0, r1);
    }

    __syncthreads();

    // Coalesced vectorized store of the block's [256 x 32] tile.
    float4* __restrict__ out4 = (float4*)(out + (long long)blockIdx.x * BLOCK * 32);
#pragma unroll
    for (int i = tid; i < BLOCK * 8; i += BLOCK) {
        const int pp = i >> 3;
        const int e4 = i & 7;
        out4[i] = *(const float4*)&s_out[pp * SPITCH + e4 * 4];
    }
}

extern "C" void kernel_launch(void* const* d_in, const int* in_sizes, int n_in,
                              void* d_out, int out_size)
{
    const float* in  = (const float*)d_in[0];   // [B,3] float32
    const float* emb = (const float*)d_in[1];   // [TOTAL_PARAMS,2] float32
    float* out = (float*)d_out;                 // [B,32] float32

    hash_encode_kernel<<<NPOINTS / BLOCK, BLOCK>>>(in, emb, out);
}

// round 8
// speedup vs baseline: 1.7658x; 1.7658x over previous
#include <cuda_runtime.h>

// HashEncoder: D=3, L=16, C=2, BASE=16, PLS=2, T=2^19, B=2^21
// Levels 0..2 dense, levels 3..15 hashed into T=524288 entries.
// Output: [B, 32] float32.
//
// Lane-pair scheme: 2 consecutive lanes process ONE point; even lane owns
// x-corner 0, odd lane owns x-corner 1. Their gather addresses differ only
// in the low index bits (~75% of pairs land in the same 32B L2 sector), so
// the L1 coalescer merges them within each warp-gather -> ~0.625x the
// scattered-wavefront floor of the 1-thread-per-point kernel.
// Plain LDG.64 everywhere (128-bit gathers measured ~2x per-wavefront cost).

#define NPOINTS  2097152
#define NLEV     16
#define TSIZE    524288u
#define HMASK    524287u
#define PRIME1   2654435761u
#define PRIME2   805459861u
#define BLOCK    256
#define PTS_BLK  128          // 16 points per warp * 8 warps
#define SPITCH   36           // floats per point row in smem

__device__ static constexpr int OFFS[16] = {
    0, 4096, 36864, 299008,
    823296, 1347584, 1871872, 2396160,
    2920448, 3444736, 3969024, 4493312,
    5017600, 5541888, 6066176, 6590464
};

__global__ void __launch_bounds__(BLOCK)
hash_encode_kernel(const float* __restrict__ in,
                   const float* __restrict__ emb,
                   float* __restrict__ out)
{
    __shared__ float s_out[PTS_BLK * SPITCH];   // 18 KB

    const int tid  = threadIdx.x;
    const int lane = tid & 31;
    const int s    = lane & 1;          // 0 -> x-corner 0, 1 -> x-corner 1
    const int qb   = (tid >> 5) * 16 + (lane >> 1);   // point within block
    const long long p = (long long)blockIdx.x * PTS_BLK + qb;

    const float x = in[p * 3 + 0];
    const float y = in[p * 3 + 1];
    const float z = in[p * 3 + 2];

#pragma unroll
    for (int l = 0; l < NLEV; l++) {
        const int res = 16 << l;                 // exact: ceil(16 * 2^l)
        const float scale = (float)(res - 1);

        const float px = x * scale;
        const float py = y * scale;
        const float pz = z * scale;

        // Base corner clamped to res-2; frac may reach 1.0 (equivalent to the
        // reference's per-corner clamp: boundary corner gets w=1, other w=0).
        const int ix0 = min(__float2int_rd(px), res - 2);
        const int iy0 = min(__float2int_rd(py), res - 2);
        const int iz0 = min(__float2int_rd(pz), res - 2);

        const float fx = px - (float)ix0;
        const float fy = py - (float)iy0;
        const float fz = pz - (float)iz0;

        // This lane's x-corner weight and coordinate.
        const float wxs = s ? fx : (1.0f - fx);
        const unsigned ux = (unsigned)ix0 + (unsigned)s;

        const float wyz[4] = {(1.0f - fy) * (1.0f - fz),
                              fy * (1.0f - fz),
                              (1.0f - fy) * fz,
                              fy * fz};

        const float2* __restrict__ e = (const float2*)emb + OFFS[l];
        const bool dense = ((long long)res * res * res) <= (long long)TSIZE; // compile-time

        unsigned idx[4];
        if (dense) {
            const unsigned r  = (unsigned)res;
            const unsigned r2 = r * r;
            const unsigned b00 = (unsigned)iy0 * r        + (unsigned)iz0 * r2;
            const unsigned b10 = b00 + r;
            const unsigned b01 = b00 + r2;
            const unsigned b11 = b01 + r;
            idx[0] = ux + b00; idx[1] = ux + b10;
            idx[2] = ux + b01; idx[3] = ux + b11;
        } else {
            const unsigned hy0 = (unsigned)iy0 * PRIME1;
            const unsigned hy1 = hy0 + PRIME1;
            const unsigned hz0 = (unsigned)iz0 * PRIME2;
            const unsigned hz1 = hz0 + PRIME2;
            idx[0] = (ux ^ hy0 ^ hz0) & HMASK;
            idx[1] = (ux ^ hy1 ^ hz0) & HMASK;
            idx[2] = (ux ^ hy0 ^ hz1) & HMASK;
            idx[3] = (ux ^ hy1 ^ hz1) & HMASK;
        }

        // Batch the 4 gathers, then pure FMAs.
        float2 v0 = __ldg(e + idx[0]);
        float2 v1 = __ldg(e + idx[1]);
        float2 v2 = __ldg(e + idx[2]);
        float2 v3 = __ldg(e + idx[3]);

        float r0, r1;
        r0 = wyz[0] * v0.x;             r1 = wyz[0] * v0.y;
        r0 = fmaf(wyz[1], v1.x, r0);    r1 = fmaf(wyz[1], v1.y, r1);
        r0 = fmaf(wyz[2], v2.x, r0);    r1 = fmaf(wyz[2], v2.y, r1);
        r0 = fmaf(wyz[3], v3.x, r0);    r1 = fmaf(wyz[3], v3.y, r1);
        r0 *= wxs;                      r1 *= wxs;

        // Combine the two x-corners across the lane pair.
        r0 += __shfl_xor_sync(0xFFFFFFFFu, r0, 1);
        r1 += __shfl_xor_sync(0xFFFFFFFFu, r1, 1);

        if (s == 0)
            *(float2*)&s_out[qb * SPITCH + 2 * l] = make_float2(r0, r1);
    }

    __syncthreads();

    // Coalesced vectorized store of the block's [128 x 32] tile.
    float4* __restrict__ out4 = (float4*)(out + (long long)blockIdx.x * PTS_BLK * 32);
#pragma unroll
    for (int i = tid; i < PTS_BLK * 8; i += BLOCK) {
        const int pp = i >> 3;
        const int e4 = i & 7;
        out4[i] = *(const float4*)&s_out[pp * SPITCH + e4 * 4];
    }
}

extern "C" void kernel_launch(void* const* d_in, const int* in_sizes, int n_in,
                              void* d_out, int out_size)
{
    const float* in  = (const float*)d_in[0];   // [B,3] float32
    const float* emb = (const float*)d_in[1];   // [TOTAL_PARAMS,2] float32
    float* out = (float*)d_out;                 // [B,32] float32

    hash_encode_kernel<<<NPOINTS / PTS_BLK, BLOCK>>>(in, emb, out);
}